// round 1
// baseline (speedup 1.0000x reference)
#include <cuda_runtime.h>
#include <math.h>
#include <stdint.h>

#define NCONF 8192
#define NT 64
#define NX 64

__device__ int   g_T0[NCONF];
__device__ float g_logabsdet;

// ---------------------------------------------------------------------------
// Kernel 1: T0[i] = min( argmin_t |phi[i,t,0]| , argmin_t |phi[i,t,1]| )
// One warp per config. Each lane loads phi[i, lane, 0:2] and phi[i, lane+32, 0:2]
// as float2, then warp-shuffle argmin with first-index tie-break (jnp.argmin).
// ---------------------------------------------------------------------------
__global__ void t0_kernel(const float* __restrict__ phi) {
    int warp = (blockIdx.x * blockDim.x + threadIdx.x) >> 5;
    if (warp >= NCONF) return;
    int lane = threadIdx.x & 31;
    const float* p = phi + (size_t)warp * (NT * NX);
    float2 v0 = *reinterpret_cast<const float2*>(p + (size_t)lane * NX);
    float2 v1 = *reinterpret_cast<const float2*>(p + (size_t)(lane + 32) * NX);

    float b0 = fabsf(v0.x); int j0 = lane;
    float c0 = fabsf(v1.x);
    if (c0 < b0) { b0 = c0; j0 = lane + 32; }   // tie keeps smaller index
    float b1 = fabsf(v0.y); int j1 = lane;
    float c1 = fabsf(v1.y);
    if (c1 < b1) { b1 = c1; j1 = lane + 32; }

    #pragma unroll
    for (int off = 16; off > 0; off >>= 1) {
        float ob = __shfl_down_sync(0xffffffffu, b0, off);
        int   oj = __shfl_down_sync(0xffffffffu, j0, off);
        if (ob < b0 || (ob == b0 && oj < j0)) { b0 = ob; j0 = oj; }
        ob = __shfl_down_sync(0xffffffffu, b1, off);
        oj = __shfl_down_sync(0xffffffffu, j1, off);
        if (ob < b1 || (ob == b1 && oj < j1)) { b1 = ob; j1 = oj; }
    }
    if (lane == 0) g_T0[warp] = (j0 > j1) ? j1 : j0;   // where(t0>t1, t1, t0)
}

// ---------------------------------------------------------------------------
// Kernel 2: log|det W| via LU with partial pivoting, one block of 64 threads.
// Column-parallel elimination; warp-shuffle pivot search. Runs once per launch.
// ---------------------------------------------------------------------------
__global__ void lu_kernel(const float* __restrict__ W) {
    __shared__ float A[64][65];
    __shared__ float m[64];
    __shared__ float rv[2];
    __shared__ int   ri[2];
    int tid = threadIdx.x;   // 64 threads

    for (int idx = tid; idx < 64 * 64; idx += 64)
        A[idx >> 6][idx & 63] = W[idx];
    __syncthreads();

    float ld = 0.0f;
    for (int k = 0; k < 64; ++k) {
        // pivot search over rows >= k
        float v  = (tid >= k) ? fabsf(A[tid][k]) : -1.0f;
        int   vi = tid;
        #pragma unroll
        for (int off = 16; off > 0; off >>= 1) {
            float ov = __shfl_down_sync(0xffffffffu, v,  off);
            int   oi = __shfl_down_sync(0xffffffffu, vi, off);
            if (ov > v) { v = ov; vi = oi; }
        }
        if ((tid & 31) == 0) { rv[tid >> 5] = v; ri[tid >> 5] = vi; }
        __syncthreads();
        int p = (rv[1] > rv[0]) ? ri[1] : ri[0];

        // swap rows k <-> p (columns parallel)
        if (p != k) {
            float t1 = A[k][tid], t2 = A[p][tid];
            A[k][tid] = t2; A[p][tid] = t1;
        }
        __syncthreads();

        float piv = A[k][k];
        ld += logf(fabsf(piv));
        if (tid > k) m[tid] = A[tid][k] / piv;
        __syncthreads();

        // eliminate: thread owns column `tid`, rows k+1..63
        if (tid > k) {
            float akj = A[k][tid];
            for (int r = k + 1; r < 64; ++r)
                A[r][tid] -= m[r] * akj;
        }
        __syncthreads();
    }
    if (tid == 0) g_logabsdet = ld;
}

// ---------------------------------------------------------------------------
// Kernel 3: per-config GEMM against doubly-rolled W.
//   C[t,j] = sum_u phiT[u,t] * Wr[u,j] + br[j]
// where Wr[u,j] = W[(u+T0)%64, (j+T0)%64], br[j] = b[(j+T0)%64].
// One CTA per config, 256 threads, each computes a 4x4 output tile.
// Inner product uses packed fma.rn.f32x2 (2 fp32 FMAs per issue).
// ---------------------------------------------------------------------------
__global__ void __launch_bounds__(256) gemm_kernel(
    const float* __restrict__ phi, const float* __restrict__ W,
    const float* __restrict__ b, float* __restrict__ out, int write_logdet)
{
    __shared__ float sphiT[64][68];   // [u][t], padded row stride 68
    __shared__ float sWr[64][64];     // rolled W
    __shared__ float sbr[64];         // rolled b

    int i   = blockIdx.x;
    int tid = threadIdx.x;
    int T0  = g_T0[i];

    // --- load phi tile, transpose 4x4 blocks in registers ---
    {
        int c = tid & 15, a = tid >> 4;   // c: u-block, a: t-block
        const float4* g4 = reinterpret_cast<const float4*>(phi + (size_t)i * (NT * NX));
        float4 r0 = g4[(4 * a + 0) * 16 + c];
        float4 r1 = g4[(4 * a + 1) * 16 + c];
        float4 r2 = g4[(4 * a + 2) * 16 + c];
        float4 r3 = g4[(4 * a + 3) * 16 + c];
        *reinterpret_cast<float4*>(&sphiT[4 * c + 0][4 * a]) = make_float4(r0.x, r1.x, r2.x, r3.x);
        *reinterpret_cast<float4*>(&sphiT[4 * c + 1][4 * a]) = make_float4(r0.y, r1.y, r2.y, r3.y);
        *reinterpret_cast<float4*>(&sphiT[4 * c + 2][4 * a]) = make_float4(r0.z, r1.z, r2.z, r3.z);
        *reinterpret_cast<float4*>(&sphiT[4 * c + 3][4 * a]) = make_float4(r0.w, r1.w, r2.w, r3.w);
    }

    // --- load doubly-rolled W (hits L2: same 16KB for all CTAs) ---
    #pragma unroll
    for (int kk = 0; kk < 16; ++kk) {
        int idx = tid + kk * 256;
        int u = idx >> 6, j = idx & 63;
        sWr[u][j] = W[(((u + T0) & 63) << 6) | ((j + T0) & 63)];
    }
    if (tid < 64) sbr[tid] = b[(tid + T0) & 63];
    __syncthreads();

    int tx = tid & 15, ty = tid >> 4;
    const float* aBase = &sphiT[0][4 * ty];
    const float* wBase = &sWr[0][4 * tx];

    unsigned long long acc00 = 0ull, acc01 = 0ull, acc10 = 0ull, acc11 = 0ull,
                       acc20 = 0ull, acc21 = 0ull, acc30 = 0ull, acc31 = 0ull;

    #pragma unroll
    for (int u = 0; u < 64; ++u) {
        float4     av = *reinterpret_cast<const float4*>(aBase + u * 68);
        ulonglong2 wv = *reinterpret_cast<const ulonglong2*>(wBase + u * 64);
        unsigned long long a0, a1, a2, a3;
        asm("mov.b64 %0, {%1, %1};" : "=l"(a0) : "r"(__float_as_uint(av.x)));
        asm("mov.b64 %0, {%1, %1};" : "=l"(a1) : "r"(__float_as_uint(av.y)));
        asm("mov.b64 %0, {%1, %1};" : "=l"(a2) : "r"(__float_as_uint(av.z)));
        asm("mov.b64 %0, {%1, %1};" : "=l"(a3) : "r"(__float_as_uint(av.w)));
        asm("fma.rn.f32x2 %0, %1, %2, %0;" : "+l"(acc00) : "l"(a0), "l"(wv.x));
        asm("fma.rn.f32x2 %0, %1, %2, %0;" : "+l"(acc01) : "l"(a0), "l"(wv.y));
        asm("fma.rn.f32x2 %0, %1, %2, %0;" : "+l"(acc10) : "l"(a1), "l"(wv.x));
        asm("fma.rn.f32x2 %0, %1, %2, %0;" : "+l"(acc11) : "l"(a1), "l"(wv.y));
        asm("fma.rn.f32x2 %0, %1, %2, %0;" : "+l"(acc20) : "l"(a2), "l"(wv.x));
        asm("fma.rn.f32x2 %0, %1, %2, %0;" : "+l"(acc21) : "l"(a2), "l"(wv.y));
        asm("fma.rn.f32x2 %0, %1, %2, %0;" : "+l"(acc30) : "l"(a3), "l"(wv.x));
        asm("fma.rn.f32x2 %0, %1, %2, %0;" : "+l"(acc31) : "l"(a3), "l"(wv.y));
    }

    // --- epilogue: unpack, add rolled bias, store coalesced float4 ---
    float b0v = sbr[4 * tx + 0], b1v = sbr[4 * tx + 1];
    float b2v = sbr[4 * tx + 2], b3v = sbr[4 * tx + 3];

    union F2 { unsigned long long u; float2 f; };
    float* orow = out + ((size_t)i * NT + 4 * ty) * NX + 4 * tx;

    {
        F2 lo, hi; lo.u = acc00; hi.u = acc01;
        *reinterpret_cast<float4*>(orow + 0 * NX) =
            make_float4(lo.f.x + b0v, lo.f.y + b1v, hi.f.x + b2v, hi.f.y + b3v);
    }
    {
        F2 lo, hi; lo.u = acc10; hi.u = acc11;
        *reinterpret_cast<float4*>(orow + 1 * NX) =
            make_float4(lo.f.x + b0v, lo.f.y + b1v, hi.f.x + b2v, hi.f.y + b3v);
    }
    {
        F2 lo, hi; lo.u = acc20; hi.u = acc21;
        *reinterpret_cast<float4*>(orow + 2 * NX) =
            make_float4(lo.f.x + b0v, lo.f.y + b1v, hi.f.x + b2v, hi.f.y + b3v);
    }
    {
        F2 lo, hi; lo.u = acc30; hi.u = acc31;
        *reinterpret_cast<float4*>(orow + 3 * NX) =
            make_float4(lo.f.x + b0v, lo.f.y + b1v, hi.f.x + b2v, hi.f.y + b3v);
    }

    if (write_logdet && tid == 0)
        out[(size_t)NCONF * NT * NX + i] = (float)NT * g_logabsdet;
}

// ---------------------------------------------------------------------------
extern "C" void kernel_launch(void* const* d_in, const int* in_sizes, int n_in,
                              void* d_out, int out_size) {
    const float* phi = nullptr;
    const float* W   = nullptr;
    const float* b   = nullptr;
    for (int k = 0; k < n_in; ++k) {
        if      (in_sizes[k] == NCONF * NT * NX) phi = (const float*)d_in[k];
        else if (in_sizes[k] == NX * NX)         W   = (const float*)d_in[k];
        else if (in_sizes[k] == NX)              b   = (const float*)d_in[k];
    }
    float* out = (float*)d_out;
    int write_logdet = (out_size >= NCONF * NT * NX + NCONF) ? 1 : 0;

    t0_kernel<<<NCONF / 8, 256>>>(phi);
    lu_kernel<<<1, 64>>>(W);
    gemm_kernel<<<NCONF, 256>>>(phi, W, b, out, write_logdet);
}